// round 4
// baseline (speedup 1.0000x reference)
#include <cuda_runtime.h>
#include <cstdint>

// Problem shape (fixed by the dataset; N/E also derived from in_sizes at launch).
#define MAXN 10240          // >= 10000 nodes
#define C    128            // channels
#define BF   16             // bond features

// Scratch: __device__ globals (no allocation allowed).
__device__ __align__(128) float g_accum[MAXN * C];   // scatter-sum target [N, C]
__device__ int   g_deg_row[MAXN];
__device__ int   g_deg_col[MAXN];
__device__ float g_inv_row[MAXN];
__device__ float g_inv_col[MAXN];

// ---------------------------------------------------------------------------
// Kernel 1: zero accumulator, init degrees to 1 (the self-loop contribution).
// ---------------------------------------------------------------------------
__global__ void k_init(int N) {
    int i = blockIdx.x * blockDim.x + threadIdx.x;
    if (i < N * C) g_accum[i] = 0.0f;
    if (i < N) { g_deg_row[i] = 1; g_deg_col[i] = 1; }
}

// ---------------------------------------------------------------------------
// Kernel 2: degree histograms over edge_index (row = ei[0:E], col = ei[E:2E]).
// ---------------------------------------------------------------------------
__global__ void k_deg(const int* __restrict__ ei, int E) {
    int e = blockIdx.x * blockDim.x + threadIdx.x;
    if (e >= E) return;
    atomicAdd(&g_deg_row[ei[e]], 1);
    atomicAdd(&g_deg_col[ei[E + e]], 1);
}

// ---------------------------------------------------------------------------
// Kernel 3: inverse-sqrt degree tables. deg >= 1 always (self-loops).
// ---------------------------------------------------------------------------
__global__ void k_inv(int N) {
    int i = blockIdx.x * blockDim.x + threadIdx.x;
    if (i >= N) return;
    g_inv_row[i] = rsqrtf((float)g_deg_row[i]);
    g_inv_col[i] = rsqrtf((float)g_deg_col[i]);
}

// ---------------------------------------------------------------------------
// Kernel 4: message kernel. One warp per (edge or self-loop).
//   emb  = edge_attr[e] @ W_bond + b_bond        (f32x2 packed FMA)
//   msg  = gelu(x[row] + emb) * invdeg(row)*invdeg(col) * ew
//   red.global.add.v4.f32 into g_accum[col]
// Lanes: lane handles channels [4*lane, 4*lane+4).
// ---------------------------------------------------------------------------
__device__ __forceinline__ float gelu_exact(float v) {
    return 0.5f * v * (1.0f + erff(v * 0.70710678118654752440f));
}

__global__ __launch_bounds__(256) void k_msg(
    const float* __restrict__ x,
    const float* __restrict__ edge_attr,
    const float* __restrict__ ew,
    const float* __restrict__ Wb,
    const float* __restrict__ bb,
    const int*   __restrict__ ei,
    int E, int N)
{
    __shared__ __align__(16) float sW[BF * C];   // 8 KB
    __shared__ __align__(16) float sb[C];        // 512 B

    const int tid = threadIdx.x;
    for (int i = tid; i < BF * C; i += 256) sW[i] = Wb[i];
    if (tid < C) sb[tid] = bb[tid];
    __syncthreads();

    const int lane = tid & 31;
    const int warp = tid >> 5;
    const int e = blockIdx.x * 8 + warp;          // 8 warps per block
    const int total = E + N;                      // real edges + self-loops
    if (e >= total) return;

    int row, col;
    float w;
    float e0, e1, e2, e3;                         // emb channels for this lane

    if (e < E) {
        row = ei[e];
        col = ei[E + e];
        w   = ew[e];

        // Bond encoder: acc = b_bond + sum_k attr[k] * W_bond[k, :]
        // Packed f32x2 accumulation -> FFMA2 in SASS (half the FMA-pipe ops).
        const float4 bv = ((const float4*)sb)[lane];
        unsigned long long acc01, acc23;
        asm("mov.b64 %0, {%1, %2};" : "=l"(acc01) : "f"(bv.x), "f"(bv.y));
        asm("mov.b64 %0, {%1, %2};" : "=l"(acc23) : "f"(bv.z), "f"(bv.w));

        const float a_my = edge_attr[(size_t)e * BF + (lane & 15)];
        const ulonglong2* sW2 = (const ulonglong2*)sW;   // same bits as float4
        #pragma unroll
        for (int k = 0; k < BF; ++k) {
            const float ak = __shfl_sync(0xffffffffu, a_my, k);
            unsigned long long ak2;
            asm("mov.b64 %0, {%1, %1};" : "=l"(ak2) : "f"(ak));
            const ulonglong2 wv = sW2[k * 32 + lane];    // LDS.128
            asm("fma.rn.f32x2 %0, %1, %2, %0;" : "+l"(acc01) : "l"(wv.x), "l"(ak2));
            asm("fma.rn.f32x2 %0, %1, %2, %0;" : "+l"(acc23) : "l"(wv.y), "l"(ak2));
        }
        asm("mov.b64 {%0, %1}, %2;" : "=f"(e0), "=f"(e1) : "l"(acc01));
        asm("mov.b64 {%0, %1}, %2;" : "=f"(e2), "=f"(e3) : "l"(acc23));
    } else {
        // self-loop: zero embedding, unit edge weight
        row = col = e - E;
        w = 1.0f;
        e0 = e1 = e2 = e3 = 0.0f;
    }

    const float norm = g_inv_row[row] * g_inv_col[col] * w;

    const float4 xv = ((const float4*)x)[row * 32 + lane];
    float m0 = gelu_exact(xv.x + e0) * norm;
    float m1 = gelu_exact(xv.y + e1) * norm;
    float m2 = gelu_exact(xv.z + e2) * norm;
    float m3 = gelu_exact(xv.w + e3) * norm;

    float* dst = &g_accum[(size_t)col * C + lane * 4];
    asm volatile("red.global.add.v4.f32 [%0], {%1, %2, %3, %4};"
                 :: "l"(dst), "f"(m0), "f"(m1), "f"(m2), "f"(m3) : "memory");
}

// ---------------------------------------------------------------------------
// Kernel 5: out = g_accum @ W_lin + b_lin.
// Block = 128 threads handles 8 node rows; W_lin column streamed once per
// 8 rows (64 KB, L1-resident across blocks). Thread j owns output channel j.
// ---------------------------------------------------------------------------
__global__ __launch_bounds__(128) void k_out(
    const float* __restrict__ Wl,
    const float* __restrict__ bl,
    float* __restrict__ out,
    int N)
{
    __shared__ float sx[8][C];
    const int n0 = blockIdx.x * 8;
    const int j  = threadIdx.x;

    #pragma unroll
    for (int r = 0; r < 8; ++r) {
        int n = n0 + r;
        sx[r][j] = (n < N) ? g_accum[(size_t)n * C + j] : 0.0f;
    }
    __syncthreads();

    float a0 = 0.f, a1 = 0.f, a2 = 0.f, a3 = 0.f;
    float a4 = 0.f, a5 = 0.f, a6 = 0.f, a7 = 0.f;
    #pragma unroll 4
    for (int c = 0; c < C; ++c) {
        const float wv = Wl[c * C + j];
        a0 += sx[0][c] * wv;  a1 += sx[1][c] * wv;
        a2 += sx[2][c] * wv;  a3 += sx[3][c] * wv;
        a4 += sx[4][c] * wv;  a5 += sx[5][c] * wv;
        a6 += sx[6][c] * wv;  a7 += sx[7][c] * wv;
    }
    const float b = bl[j];
    float acc[8] = {a0, a1, a2, a3, a4, a5, a6, a7};
    #pragma unroll
    for (int r = 0; r < 8; ++r) {
        int n = n0 + r;
        if (n < N) out[(size_t)n * C + j] = acc[r] + b;
    }
}

// ---------------------------------------------------------------------------
// Launch: linear chain of 5 kernels on the capture stream.
// ---------------------------------------------------------------------------
extern "C" void kernel_launch(void* const* d_in, const int* in_sizes, int n_in,
                              void* d_out, int out_size)
{
    const float* x         = (const float*)d_in[0];   // [N, 128]
    const float* edge_attr = (const float*)d_in[1];   // [E, 16]
    const float* ew        = (const float*)d_in[2];   // [E, 1]
    const float* Wb        = (const float*)d_in[3];   // [16, 128]
    const float* bb        = (const float*)d_in[4];   // [128]
    const float* Wl        = (const float*)d_in[5];   // [128, 128]
    const float* bl        = (const float*)d_in[6];   // [128]
    const int*   ei        = (const int*)d_in[7];     // [2, E]
    float*       out       = (float*)d_out;           // [N, 128]

    const int E = in_sizes[2];          // edge_weight element count
    const int N = in_sizes[0] / C;      // x rows

    {   // init: covers N*C accumulator elements (N*C >= N, >= 2N)
        int threads = 256;
        int blocks = (N * C + threads - 1) / threads;
        k_init<<<blocks, threads>>>(N);
    }
    {
        int threads = 256;
        int blocks = (E + threads - 1) / threads;
        k_deg<<<blocks, threads>>>(ei, E);
    }
    {
        int threads = 256;
        int blocks = (N + threads - 1) / threads;
        k_inv<<<blocks, threads>>>(N);
    }
    {
        int total = E + N;                        // edges + self-loops
        int blocks = (total + 7) / 8;             // 8 warps (edges) per block
        k_msg<<<blocks, 256>>>(x, edge_attr, ew, Wb, bb, ei, E, N);
    }
    {
        int blocks = (N + 7) / 8;
        k_out<<<blocks, 128>>>(Wl, bl, out, N);
    }
}

// round 5
// speedup vs baseline: 1.4040x; 1.4040x over previous
#include <cuda_runtime.h>
#include <cstdint>

#define MAXN 10240          // >= 10000 nodes
#define C    128            // channels
#define BF   16             // bond features

// Scratch: __device__ globals (no allocation allowed).
__device__ __align__(128) float g_accum[MAXN * C];   // scatter-sum target [N, C]
__device__ int   g_deg_row[MAXN];
__device__ int   g_deg_col[MAXN];
__device__ float g_inv_row[MAXN];
__device__ float g_inv_col[MAXN];

// ---------------------------------------------------------------------------
// Kernel 1: zero accumulator, init degrees to 1 (the self-loop contribution).
// ---------------------------------------------------------------------------
__global__ void k_init(int N) {
    int i = blockIdx.x * blockDim.x + threadIdx.x;
    if (i < N * C) g_accum[i] = 0.0f;
    if (i < N) { g_deg_row[i] = 1; g_deg_col[i] = 1; }
}

// ---------------------------------------------------------------------------
// Kernel 2: degree histograms. 4 edges per thread via int4 loads.
// ---------------------------------------------------------------------------
__global__ void k_deg(const int* __restrict__ ei, int E) {
    int t = blockIdx.x * blockDim.x + threadIdx.x;
    int e = t * 4;
    if (e + 3 < E) {
        int4 r = *(const int4*)(ei + e);
        int4 c = *(const int4*)(ei + E + e);
        atomicAdd(&g_deg_row[r.x], 1); atomicAdd(&g_deg_row[r.y], 1);
        atomicAdd(&g_deg_row[r.z], 1); atomicAdd(&g_deg_row[r.w], 1);
        atomicAdd(&g_deg_col[c.x], 1); atomicAdd(&g_deg_col[c.y], 1);
        atomicAdd(&g_deg_col[c.z], 1); atomicAdd(&g_deg_col[c.w], 1);
    } else {
        for (; e < E; ++e) {
            atomicAdd(&g_deg_row[ei[e]], 1);
            atomicAdd(&g_deg_col[ei[E + e]], 1);
        }
    }
}

// ---------------------------------------------------------------------------
// Kernel 3: inverse-sqrt degree tables. deg >= 1 always (self-loops).
// ---------------------------------------------------------------------------
__global__ void k_inv(int N) {
    int i = blockIdx.x * blockDim.x + threadIdx.x;
    if (i >= N) return;
    g_inv_row[i] = rsqrtf((float)g_deg_row[i]);
    g_inv_col[i] = rsqrtf((float)g_deg_col[i]);
}

// ---------------------------------------------------------------------------
// Kernel 4: persistent message kernel. Grid-stride over (edges + self-loops),
// one warp per edge per iteration. W_bond slice for this lane's 4 channels
// lives in 32 packed-b64 REGISTERS (loaded once per warp, amortized over
// ~275 edges) -> zero per-edge SMEM traffic.
//   emb  = edge_attr[e] @ W_bond + b_bond        (FFMA2 on packed f32x2)
//   msg  = gelu(x[row] + emb) * invdeg(row)*invdeg(col) * ew
//   red.global.add.v4.f32 into g_accum[col]
// ---------------------------------------------------------------------------
__global__ __launch_bounds__(128, 4) void k_msg(
    const float* __restrict__ x,
    const float* __restrict__ edge_attr,
    const float* __restrict__ ew,
    const float* __restrict__ Wb,
    const float* __restrict__ bb,
    const int*   __restrict__ ei,
    int E, int N)
{
    const int lane = threadIdx.x & 31;
    const int warp = threadIdx.x >> 5;
    const int gw   = blockIdx.x * 4 + warp;           // global warp id
    const int gstride = gridDim.x * 4;
    const int total = E + N;                          // real edges + self-loops

    // --- per-warp setup: W_bond slice + bias into registers (amortized) ---
    // Lane owns channels [4*lane, 4*lane+4). Row k of W is 128 floats.
    unsigned long long W01[BF], W23[BF];
    #pragma unroll
    for (int k = 0; k < BF; ++k) {
        const ulonglong2 wv = ((const ulonglong2*)Wb)[k * 32 + lane];  // LDG.128
        W01[k] = wv.x;
        W23[k] = wv.y;
    }
    unsigned long long bias01, bias23;
    {
        const float4 bv = ((const float4*)bb)[lane];
        asm("mov.b64 %0, {%1, %2};" : "=l"(bias01) : "f"(bv.x), "f"(bv.y));
        asm("mov.b64 %0, {%1, %2};" : "=l"(bias23) : "f"(bv.z), "f"(bv.w));
    }

    for (int e = gw; e < total; e += gstride) {
        int row, col;
        float w;
        unsigned long long acc01, acc23;

        if (e < E) {
            row = __ldg(ei + e);
            col = __ldg(ei + E + e);
            w   = __ldg(ew + e);

            acc01 = bias01;
            acc23 = bias23;

            const float a_my = __ldg(edge_attr + (size_t)e * BF + (lane & 15));
            #pragma unroll
            for (int k = 0; k < BF; ++k) {
                const float ak = __shfl_sync(0xffffffffu, a_my, k);
                unsigned long long ak2;
                asm("mov.b64 %0, {%1, %1};" : "=l"(ak2) : "f"(ak));
                asm("fma.rn.f32x2 %0, %1, %2, %0;" : "+l"(acc01) : "l"(W01[k]), "l"(ak2));
                asm("fma.rn.f32x2 %0, %1, %2, %0;" : "+l"(acc23) : "l"(W23[k]), "l"(ak2));
            }
        } else {
            // self-loop: zero embedding, unit edge weight
            row = col = e - E;
            w = 1.0f;
            acc01 = 0ull;
            acc23 = 0ull;
        }

        float e0, e1, e2, e3;
        asm("mov.b64 {%0, %1}, %2;" : "=f"(e0), "=f"(e1) : "l"(acc01));
        asm("mov.b64 {%0, %1}, %2;" : "=f"(e2), "=f"(e3) : "l"(acc23));

        const float h = 0.5f * g_inv_row[row] * g_inv_col[col] * w;

        const float4 xv = ((const float4*)x)[row * 32 + lane];
        const float v0 = xv.x + e0, v1 = xv.y + e1;
        const float v2 = xv.z + e2, v3 = xv.w + e3;

        // gelu(v)*norm = (v*h) + (v*h)*erf(v/sqrt2)
        const float t0 = erff(v0 * 0.70710678118654752440f);
        const float t1 = erff(v1 * 0.70710678118654752440f);
        const float t2 = erff(v2 * 0.70710678118654752440f);
        const float t3 = erff(v3 * 0.70710678118654752440f);
        const float vh0 = v0 * h, vh1 = v1 * h, vh2 = v2 * h, vh3 = v3 * h;
        const float m0 = fmaf(vh0, t0, vh0);
        const float m1 = fmaf(vh1, t1, vh1);
        const float m2 = fmaf(vh2, t2, vh2);
        const float m3 = fmaf(vh3, t3, vh3);

        float* dst = &g_accum[(size_t)col * C + lane * 4];
        asm volatile("red.global.add.v4.f32 [%0], {%1, %2, %3, %4};"
                     :: "l"(dst), "f"(m0), "f"(m1), "f"(m2), "f"(m3) : "memory");
    }
}

// ---------------------------------------------------------------------------
// Kernel 5: out = g_accum @ W_lin + b_lin.
// Block = 128 threads handles 8 node rows; W_lin L1-resident across blocks.
// ---------------------------------------------------------------------------
__global__ __launch_bounds__(128) void k_out(
    const float* __restrict__ Wl,
    const float* __restrict__ bl,
    float* __restrict__ out,
    int N)
{
    __shared__ float sx[8][C];
    const int n0 = blockIdx.x * 8;
    const int j  = threadIdx.x;

    #pragma unroll
    for (int r = 0; r < 8; ++r) {
        int n = n0 + r;
        sx[r][j] = (n < N) ? g_accum[(size_t)n * C + j] : 0.0f;
    }
    __syncthreads();

    float a0 = 0.f, a1 = 0.f, a2 = 0.f, a3 = 0.f;
    float a4 = 0.f, a5 = 0.f, a6 = 0.f, a7 = 0.f;
    #pragma unroll 4
    for (int c = 0; c < C; ++c) {
        const float wv = Wl[c * C + j];
        a0 += sx[0][c] * wv;  a1 += sx[1][c] * wv;
        a2 += sx[2][c] * wv;  a3 += sx[3][c] * wv;
        a4 += sx[4][c] * wv;  a5 += sx[5][c] * wv;
        a6 += sx[6][c] * wv;  a7 += sx[7][c] * wv;
    }
    const float b = bl[j];
    float acc[8] = {a0, a1, a2, a3, a4, a5, a6, a7};
    #pragma unroll
    for (int r = 0; r < 8; ++r) {
        int n = n0 + r;
        if (n < N) out[(size_t)n * C + j] = acc[r] + b;
    }
}

// ---------------------------------------------------------------------------
// Launch: linear chain of 5 kernels on the capture stream.
// ---------------------------------------------------------------------------
extern "C" void kernel_launch(void* const* d_in, const int* in_sizes, int n_in,
                              void* d_out, int out_size)
{
    const float* x         = (const float*)d_in[0];   // [N, 128]
    const float* edge_attr = (const float*)d_in[1];   // [E, 16]
    const float* ew        = (const float*)d_in[2];   // [E, 1]
    const float* Wb        = (const float*)d_in[3];   // [16, 128]
    const float* bb        = (const float*)d_in[4];   // [128]
    const float* Wl        = (const float*)d_in[5];   // [128, 128]
    const float* bl        = (const float*)d_in[6];   // [128]
    const int*   ei        = (const int*)d_in[7];     // [2, E]
    float*       out       = (float*)d_out;           // [N, 128]

    const int E = in_sizes[2];          // edge_weight element count
    const int N = in_sizes[0] / C;      // x rows

    {   // init accumulator + degree seeds
        int threads = 256;
        int blocks = (N * C + threads - 1) / threads;
        k_init<<<blocks, threads>>>(N);
    }
    {
        int threads = 256;
        int work = (E + 3) / 4;
        int blocks = (work + threads - 1) / threads;
        k_deg<<<blocks, threads>>>(ei, E);
    }
    {
        int threads = 256;
        int blocks = (N + threads - 1) / threads;
        k_inv<<<blocks, threads>>>(N);
    }
    {
        // persistent: 152 SMs * 4 resident blocks (launch_bounds(128,4))
        k_msg<<<608, 128>>>(x, edge_attr, ew, Wb, bb, ei, E, N);
    }
    {
        int blocks = (N + 7) / 8;
        k_out<<<blocks, 128>>>(Wl, bl, out, N);
    }
}

// round 7
// speedup vs baseline: 1.6386x; 1.1670x over previous
#include <cuda_runtime.h>
#include <cstdint>

#define MAXN 10240          // >= 10000 nodes
#define C    128            // channels
#define BF   16             // bond features

// Scratch: __device__ globals (no allocation allowed).
__device__ __align__(128) float g_accum[MAXN * C];   // scatter-sum target [N, C]
__device__ int   g_deg_row[MAXN];
__device__ int   g_deg_col[MAXN];
__device__ float g_inv_row[MAXN];
__device__ float g_inv_col[MAXN];

// ---------------------------------------------------------------------------
// Kernel 1: zero accumulator (float4), init degrees to 1 (self-loop count).
// ---------------------------------------------------------------------------
__global__ void k_init(int N) {
    int i = blockIdx.x * blockDim.x + threadIdx.x;
    if (i < N * (C / 4)) ((float4*)g_accum)[i] = make_float4(0.f, 0.f, 0.f, 0.f);
    if (i < N) { g_deg_row[i] = 1; g_deg_col[i] = 1; }
}

// ---------------------------------------------------------------------------
// Kernel 2: degree histograms. 4 edges per thread via int4 loads.
// ---------------------------------------------------------------------------
__global__ void k_deg(const int* __restrict__ ei, int E) {
    int t = blockIdx.x * blockDim.x + threadIdx.x;
    int e = t * 4;
    if (e + 3 < E) {
        int4 r = *(const int4*)(ei + e);
        int4 c = *(const int4*)(ei + E + e);
        atomicAdd(&g_deg_row[r.x], 1); atomicAdd(&g_deg_row[r.y], 1);
        atomicAdd(&g_deg_row[r.z], 1); atomicAdd(&g_deg_row[r.w], 1);
        atomicAdd(&g_deg_col[c.x], 1); atomicAdd(&g_deg_col[c.y], 1);
        atomicAdd(&g_deg_col[c.z], 1); atomicAdd(&g_deg_col[c.w], 1);
    } else {
        for (; e < E; ++e) {
            atomicAdd(&g_deg_row[ei[e]], 1);
            atomicAdd(&g_deg_col[ei[E + e]], 1);
        }
    }
}

// ---------------------------------------------------------------------------
// Kernel 3: inverse-sqrt degree tables. deg >= 1 always (self-loops).
// ---------------------------------------------------------------------------
__global__ void k_inv(int N) {
    int i = blockIdx.x * blockDim.x + threadIdx.x;
    if (i >= N) return;
    g_inv_row[i] = rsqrtf((float)g_deg_row[i]);
    g_inv_col[i] = rsqrtf((float)g_deg_col[i]);
}

// ---------------------------------------------------------------------------
// Kernel 4: persistent, 2-deep software-pipelined message kernel (REAL edges
// only; self-loops folded into k_out). One warp per edge per iteration.
//  - W_bond held in registers, k-pair packed: W2[kp][c] = {W[2kp][ch],W[2kp+1][ch]}
//  - edge_attr read as 4 uniform LDG.128 -> b64 pairs for FFMA2 directly
//  - prefetch: indices/attr/ew at distance 2*gs (idx) / 1*gs (attr actually 1-deep
//    via the rotation), x/inv at distance 1*gs -> no compute waits on a load
// ---------------------------------------------------------------------------
__global__ __launch_bounds__(128, 3) void k_msg(
    const float* __restrict__ x,
    const float* __restrict__ edge_attr,
    const float* __restrict__ ew,
    const float* __restrict__ Wb,
    const float* __restrict__ bb,
    const int*   __restrict__ ei,
    int E)
{
    const int lane = threadIdx.x & 31;
    const int gw   = blockIdx.x * 4 + (threadIdx.x >> 5);
    const int gs   = gridDim.x * 4;
    if (gw >= E) return;

    // --- per-warp setup (amortized over ~350 edges) ---
    unsigned long long W2[8][4];            // 64 regs: k-pair-major W slice
#pragma unroll
    for (int kp = 0; kp < 8; ++kp) {
        const float4 ra = __ldg((const float4*)Wb + (2*kp)   * 32 + lane);
        const float4 rb = __ldg((const float4*)Wb + (2*kp+1) * 32 + lane);
        asm("mov.b64 %0,{%1,%2};" : "=l"(W2[kp][0]) : "f"(ra.x), "f"(rb.x));
        asm("mov.b64 %0,{%1,%2};" : "=l"(W2[kp][1]) : "f"(ra.y), "f"(rb.y));
        asm("mov.b64 %0,{%1,%2};" : "=l"(W2[kp][2]) : "f"(ra.z), "f"(rb.z));
        asm("mov.b64 %0,{%1,%2};" : "=l"(W2[kp][3]) : "f"(ra.w), "f"(rb.w));
    }
    unsigned long long B0, B1, B2, B3;      // {bias, 0} accumulator seeds
    {
        const float4 bv = __ldg((const float4*)bb + lane);
        const float z = 0.0f;
        asm("mov.b64 %0,{%1,%2};" : "=l"(B0) : "f"(bv.x), "f"(z));
        asm("mov.b64 %0,{%1,%2};" : "=l"(B1) : "f"(bv.y), "f"(z));
        asm("mov.b64 %0,{%1,%2};" : "=l"(B2) : "f"(bv.z), "f"(z));
        asm("mov.b64 %0,{%1,%2};" : "=l"(B3) : "f"(bv.w), "f"(z));
    }

    // --- pipeline prologue ---
    int    r0, c0;  float w0;  float4 Aa0, Ab0, Ac0, Ad0;  // current (ready)
    float4 xv0;     float iv0;
    int    r1, c1;  float w1;  float4 Aa1, Ab1, Ac1, Ad1;  // next (idx+attr ready)

    r0 = __ldg(ei + gw); c0 = __ldg(ei + E + gw); w0 = __ldg(ew + gw);
    {
        const float4* ap = (const float4*)edge_attr + (size_t)gw * 4;
        Aa0 = __ldg(ap); Ab0 = __ldg(ap+1); Ac0 = __ldg(ap+2); Ad0 = __ldg(ap+3);
    }
    xv0 = __ldg((const float4*)x + (size_t)r0 * 32 + lane);
    iv0 = __ldg(g_inv_row + r0) * __ldg(g_inv_col + c0);

    {
        int e1 = gw + gs; int e1c = (e1 < E) ? e1 : gw;
        r1 = __ldg(ei + e1c); c1 = __ldg(ei + E + e1c); w1 = __ldg(ew + e1c);
        const float4* ap = (const float4*)edge_attr + (size_t)e1c * 4;
        Aa1 = __ldg(ap); Ab1 = __ldg(ap+1); Ac1 = __ldg(ap+2); Ad1 = __ldg(ap+3);
    }

#pragma unroll 2
    for (int e = gw; e < E; e += gs) {
        // stage 0: prefetch idx/attr/ew for e + 2*gs
        const int e2 = e + 2 * gs; const int e2c = (e2 < E) ? e2 : gw;
        const int   r2 = __ldg(ei + e2c);
        const int   c2 = __ldg(ei + E + e2c);
        const float w2 = __ldg(ew + e2c);
        const float4* ap2 = (const float4*)edge_attr + (size_t)e2c * 4;
        const float4 Aa2 = __ldg(ap2),   Ab2 = __ldg(ap2+1);
        const float4 Ac2 = __ldg(ap2+2), Ad2 = __ldg(ap2+3);

        // stage 1: prefetch x/inv for e + gs (idx already resident)
        const float4 xv1 = __ldg((const float4*)x + (size_t)r1 * 32 + lane);
        const float  iv1 = __ldg(g_inv_row + r1) * __ldg(g_inv_col + c1);

        // stage 2: compute current edge (everything already in registers)
        unsigned long long acc0 = B0, acc1 = B1, acc2 = B2, acc3 = B3;
        unsigned long long p0, p1, p2, p3, p4, p5, p6, p7;
        asm("mov.b64 %0,{%1,%2};" : "=l"(p0) : "f"(Aa0.x), "f"(Aa0.y));
        asm("mov.b64 %0,{%1,%2};" : "=l"(p1) : "f"(Aa0.z), "f"(Aa0.w));
        asm("mov.b64 %0,{%1,%2};" : "=l"(p2) : "f"(Ab0.x), "f"(Ab0.y));
        asm("mov.b64 %0,{%1,%2};" : "=l"(p3) : "f"(Ab0.z), "f"(Ab0.w));
        asm("mov.b64 %0,{%1,%2};" : "=l"(p4) : "f"(Ac0.x), "f"(Ac0.y));
        asm("mov.b64 %0,{%1,%2};" : "=l"(p5) : "f"(Ac0.z), "f"(Ac0.w));
        asm("mov.b64 %0,{%1,%2};" : "=l"(p6) : "f"(Ad0.x), "f"(Ad0.y));
        asm("mov.b64 %0,{%1,%2};" : "=l"(p7) : "f"(Ad0.z), "f"(Ad0.w));
        const unsigned long long P[8] = {p0, p1, p2, p3, p4, p5, p6, p7};
#pragma unroll
        for (int kp = 0; kp < 8; ++kp) {
            asm("fma.rn.f32x2 %0, %1, %2, %0;" : "+l"(acc0) : "l"(P[kp]), "l"(W2[kp][0]));
            asm("fma.rn.f32x2 %0, %1, %2, %0;" : "+l"(acc1) : "l"(P[kp]), "l"(W2[kp][1]));
            asm("fma.rn.f32x2 %0, %1, %2, %0;" : "+l"(acc2) : "l"(P[kp]), "l"(W2[kp][2]));
            asm("fma.rn.f32x2 %0, %1, %2, %0;" : "+l"(acc3) : "l"(P[kp]), "l"(W2[kp][3]));
        }
        float lo0, hi0, lo1, hi1, lo2, hi2, lo3, hi3;
        asm("mov.b64 {%0,%1}, %2;" : "=f"(lo0), "=f"(hi0) : "l"(acc0));
        asm("mov.b64 {%0,%1}, %2;" : "=f"(lo1), "=f"(hi1) : "l"(acc1));
        asm("mov.b64 {%0,%1}, %2;" : "=f"(lo2), "=f"(hi2) : "l"(acc2));
        asm("mov.b64 {%0,%1}, %2;" : "=f"(lo3), "=f"(hi3) : "l"(acc3));

        const float v0 = xv0.x + (lo0 + hi0);
        const float v1 = xv0.y + (lo1 + hi1);
        const float v2 = xv0.z + (lo2 + hi2);
        const float v3 = xv0.w + (lo3 + hi3);

        const float h = 0.5f * iv0 * w0;
        const float t0 = erff(v0 * 0.70710678118654752440f);
        const float t1 = erff(v1 * 0.70710678118654752440f);
        const float t2 = erff(v2 * 0.70710678118654752440f);
        const float t3 = erff(v3 * 0.70710678118654752440f);
        const float vh0 = v0 * h, vh1 = v1 * h, vh2 = v2 * h, vh3 = v3 * h;
        const float m0 = fmaf(vh0, t0, vh0);
        const float m1 = fmaf(vh1, t1, vh1);
        const float m2 = fmaf(vh2, t2, vh2);
        const float m3 = fmaf(vh3, t3, vh3);

        float* dst = &g_accum[(size_t)c0 * C + lane * 4];
        asm volatile("red.global.add.v4.f32 [%0], {%1, %2, %3, %4};"
                     :: "l"(dst), "f"(m0), "f"(m1), "f"(m2), "f"(m3) : "memory");

        // rotate pipeline registers (renamed away by the unroll)
        r0 = r1; c0 = c1; w0 = w1;
        Aa0 = Aa1; Ab0 = Ab1; Ac0 = Ac1; Ad0 = Ad1;
        xv0 = xv1; iv0 = iv1;
        r1 = r2; c1 = c2; w1 = w2;
        Aa1 = Aa2; Ab1 = Ab2; Ac1 = Ac2; Ad1 = Ad2;
    }
}

// ---------------------------------------------------------------------------
// Kernel 5: out = (g_accum + selfloop_msg) @ W_lin + b_lin.
// Self-loop message folded here: gelu(x[n]) * inv_r[n] * inv_c[n] (ew = 1).
// Block = 128 threads handles 8 node rows; W_lin L1-resident across blocks.
// ---------------------------------------------------------------------------
__global__ __launch_bounds__(128) void k_out(
    const float* __restrict__ Wl,
    const float* __restrict__ bl,
    const float* __restrict__ x,
    float* __restrict__ out,
    int N)
{
    __shared__ float sx[8][C];
    const int n0 = blockIdx.x * 8;
    const int j  = threadIdx.x;

    #pragma unroll
    for (int r = 0; r < 8; ++r) {
        int n = n0 + r;
        if (n < N) {
            const float v = x[(size_t)n * C + j];
            const float g = 0.5f * v * (1.0f + erff(v * 0.70710678118654752440f));
            const float iv = g_inv_row[n] * g_inv_col[n];
            sx[r][j] = g_accum[(size_t)n * C + j] + g * iv;
        } else {
            sx[r][j] = 0.0f;
        }
    }
    __syncthreads();

    float a0 = 0.f, a1 = 0.f, a2 = 0.f, a3 = 0.f;
    float a4 = 0.f, a5 = 0.f, a6 = 0.f, a7 = 0.f;
    #pragma unroll 4
    for (int c = 0; c < C; ++c) {
        const float wv = Wl[c * C + j];
        a0 += sx[0][c] * wv;  a1 += sx[1][c] * wv;
        a2 += sx[2][c] * wv;  a3 += sx[3][c] * wv;
        a4 += sx[4][c] * wv;  a5 += sx[5][c] * wv;
        a6 += sx[6][c] * wv;  a7 += sx[7][c] * wv;
    }
    const float b = bl[j];
    float acc[8] = {a0, a1, a2, a3, a4, a5, a6, a7};
    #pragma unroll
    for (int r = 0; r < 8; ++r) {
        int n = n0 + r;
        if (n < N) out[(size_t)n * C + j] = acc[r] + b;
    }
}

// ---------------------------------------------------------------------------
// Launch: linear chain of 5 kernels on the capture stream.
// ---------------------------------------------------------------------------
extern "C" void kernel_launch(void* const* d_in, const int* in_sizes, int n_in,
                              void* d_out, int out_size)
{
    const float* x         = (const float*)d_in[0];   // [N, 128]
    const float* edge_attr = (const float*)d_in[1];   // [E, 16]
    const float* ew        = (const float*)d_in[2];   // [E, 1]
    const float* Wb        = (const float*)d_in[3];   // [16, 128]
    const float* bb        = (const float*)d_in[4];   // [128]
    const float* Wl        = (const float*)d_in[5];   // [128, 128]
    const float* bl        = (const float*)d_in[6];   // [128]
    const int*   ei        = (const int*)d_in[7];     // [2, E]
    float*       out       = (float*)d_out;           // [N, 128]

    const int E = in_sizes[2];          // edge_weight element count
    const int N = in_sizes[0] / C;      // x rows

    {   // init accumulator (float4) + degree seeds
        int threads = 256;
        int blocks = (N * (C / 4) + threads - 1) / threads;
        k_init<<<blocks, threads>>>(N);
    }
    {
        int threads = 256;
        int work = (E + 3) / 4;
        int blocks = (work + threads - 1) / threads;
        k_deg<<<blocks, threads>>>(ei, E);
    }
    {
        int threads = 256;
        int blocks = (N + threads - 1) / threads;
        k_inv<<<blocks, threads>>>(N);
    }
    {
        // persistent: 152 SMs * 3 resident blocks (launch_bounds(128,3))
        k_msg<<<456, 128>>>(x, edge_attr, ew, Wb, bb, ei, E);
    }
    {
        int blocks = (N + 7) / 8;
        k_out<<<blocks, 128>>>(Wl, bl, x, out, N);
    }
}

// round 10
// speedup vs baseline: 1.7060x; 1.0412x over previous
#include <cuda_runtime.h>
#include <cstdint>

#define MAXN 10240          // >= 10000 nodes
#define C    128            // channels
#define BF   16             // bond features
#define T    128            // edges per SMEM tile
#define NBLK 456            // 152 SMs * 3 resident blocks

// Scratch: __device__ globals (no allocation allowed).
__device__ __align__(128) float g_accum[MAXN * C];   // scatter-sum target [N, C]
__device__ int   g_deg_row[MAXN];
__device__ int   g_deg_col[MAXN];
__device__ float g_inv_row[MAXN];
__device__ float g_inv_col[MAXN];

// ---------------------------------------------------------------------------
// Kernel 1: zero accumulator (float4), init degrees to 1 (self-loop count).
// ---------------------------------------------------------------------------
__global__ void k_init(int N) {
    int i = blockIdx.x * blockDim.x + threadIdx.x;
    if (i < N * (C / 4)) ((float4*)g_accum)[i] = make_float4(0.f, 0.f, 0.f, 0.f);
    if (i < N) { g_deg_row[i] = 1; g_deg_col[i] = 1; }
}

// ---------------------------------------------------------------------------
// Kernel 2: degree histograms. 4 edges per thread via int4 loads.
// ---------------------------------------------------------------------------
__global__ void k_deg(const int* __restrict__ ei, int E) {
    int t = blockIdx.x * blockDim.x + threadIdx.x;
    int e = t * 4;
    if (e + 3 < E) {
        int4 r = *(const int4*)(ei + e);
        int4 c = *(const int4*)(ei + E + e);
        atomicAdd(&g_deg_row[r.x], 1); atomicAdd(&g_deg_row[r.y], 1);
        atomicAdd(&g_deg_row[r.z], 1); atomicAdd(&g_deg_row[r.w], 1);
        atomicAdd(&g_deg_col[c.x], 1); atomicAdd(&g_deg_col[c.y], 1);
        atomicAdd(&g_deg_col[c.z], 1); atomicAdd(&g_deg_col[c.w], 1);
    } else {
        for (; e < E; ++e) {
            atomicAdd(&g_deg_row[ei[e]], 1);
            atomicAdd(&g_deg_col[ei[E + e]], 1);
        }
    }
}

// ---------------------------------------------------------------------------
// Kernel 3: inverse-sqrt degree tables. deg >= 1 always (self-loops).
// ---------------------------------------------------------------------------
__global__ void k_inv(int N) {
    int i = blockIdx.x * blockDim.x + threadIdx.x;
    if (i >= N) return;
    g_inv_row[i] = rsqrtf((float)g_deg_row[i]);
    g_inv_col[i] = rsqrtf((float)g_deg_col[i]);
}

// ---------------------------------------------------------------------------
// SMEM tile of staged edge data (streams decoupled from compute via cp.async)
// ---------------------------------------------------------------------------
struct __align__(16) Tile {
    float attr[T * BF];   // 8192 B
    int   row[T];         // 512 B
    int   col[T];         // 512 B
    float ew[T];          // 512 B
};

__device__ __forceinline__ void cpa16(void* s, const void* g) {
    uint32_t sa = (uint32_t)__cvta_generic_to_shared(s);
    asm volatile("cp.async.cg.shared.global [%0], [%1], 16;" :: "r"(sa), "l"(g) : "memory");
}
__device__ __forceinline__ void cp_commit() {
    asm volatile("cp.async.commit_group;" ::: "memory");
}
__device__ __forceinline__ void cp_wait1() {
    asm volatile("cp.async.wait_group 1;" ::: "memory");
}

// Stage one tile (128 threads cooperate). Fast path uses cp.async (16B,
// alignment guaranteed when base%4==0, E%4==0, full tile); tail/unaligned
// path uses plain loads+stores (zero-fill OOB).
__device__ __forceinline__ void stage_tile(
    Tile* t, int base, int E,
    const float* __restrict__ edge_attr,
    const int*   __restrict__ ei,
    const float* __restrict__ ew,
    int tid)
{
    if (base + T <= E && (E & 3) == 0) {
        const float4* asrc = (const float4*)edge_attr + (size_t)base * 4;
        #pragma unroll
        for (int j = 0; j < 4; ++j)
            cpa16(&t->attr[(tid + j * 128) * 4], asrc + tid + j * 128);
        if (tid < 32)        cpa16(&t->row[tid * 4],        ei + base + tid * 4);
        else if (tid < 64)   cpa16(&t->col[(tid - 32) * 4], ei + E + base + (tid - 32) * 4);
        else if (tid < 96)   cpa16(&t->ew [(tid - 64) * 4], ew + base + (tid - 64) * 4);
    } else {
        for (int i = tid; i < T * BF; i += 128) {
            int ge = base + (i >> 4);
            t->attr[i] = (ge < E) ? edge_attr[(size_t)ge * BF + (i & 15)] : 0.f;
        }
        if (tid < T) {
            int ge = base + tid;
            t->row[tid] = (ge < E) ? ei[ge] : 0;
            t->col[tid] = (ge < E) ? ei[E + ge] : 0;
            t->ew[tid]  = (ge < E) ? ew[ge] : 0.f;
        }
    }
}

// ---------------------------------------------------------------------------
// Kernel 4: persistent tiled message kernel.
//  - edge streams (idx/ew/attr) double-buffered in SMEM via cp.async:
//    streaming DRAM latency hidden behind a full tile (~4000 cyc) of compute
//  - W_bond register-resident, k-pair packed for FFMA2
//  - attr consumed as broadcast LDS.128 (operand pairs ready, no packing movs)
//  - x-gather: depth-2 register pipeline (indices cheap from SMEM)
//  - self-loops folded into k_out
// ---------------------------------------------------------------------------
__global__ __launch_bounds__(128, 3) void k_msg(
    const float* __restrict__ x,
    const float* __restrict__ edge_attr,
    const float* __restrict__ ew,
    const float* __restrict__ Wb,
    const float* __restrict__ bb,
    const int*   __restrict__ ei,
    int E)
{
    __shared__ Tile tiles[2];

    const int tid  = threadIdx.x;
    const int lane = tid & 31;
    const int warp = tid >> 5;
    const int ntiles = (E + T - 1) / T;
    const int t0 = blockIdx.x;
    if (t0 >= ntiles) return;

    // --- per-warp W_bond slice in registers, k-pair packed ---
    unsigned long long W2[8][4];
    #pragma unroll
    for (int kp = 0; kp < 8; ++kp) {
        const float4 ra = __ldg((const float4*)Wb + (2*kp)   * 32 + lane);
        const float4 rb = __ldg((const float4*)Wb + (2*kp+1) * 32 + lane);
        asm("mov.b64 %0,{%1,%2};" : "=l"(W2[kp][0]) : "f"(ra.x), "f"(rb.x));
        asm("mov.b64 %0,{%1,%2};" : "=l"(W2[kp][1]) : "f"(ra.y), "f"(rb.y));
        asm("mov.b64 %0,{%1,%2};" : "=l"(W2[kp][2]) : "f"(ra.z), "f"(rb.z));
        asm("mov.b64 %0,{%1,%2};" : "=l"(W2[kp][3]) : "f"(ra.w), "f"(rb.w));
    }
    unsigned long long B0, B1, B2, B3;      // {bias, 0} accumulator seeds
    {
        const float4 bv = __ldg((const float4*)bb + lane);
        const float z = 0.0f;
        asm("mov.b64 %0,{%1,%2};" : "=l"(B0) : "f"(bv.x), "f"(z));
        asm("mov.b64 %0,{%1,%2};" : "=l"(B1) : "f"(bv.y), "f"(z));
        asm("mov.b64 %0,{%1,%2};" : "=l"(B2) : "f"(bv.z), "f"(z));
        asm("mov.b64 %0,{%1,%2};" : "=l"(B3) : "f"(bv.w), "f"(z));
    }

    // --- prologue: stage first two tiles ---
    stage_tile(&tiles[0], t0 * T, E, edge_attr, ei, ew, tid);
    cp_commit();
    {
        const int t1 = t0 + gridDim.x;
        if (t1 < ntiles) stage_tile(&tiles[1], t1 * T, E, edge_attr, ei, ew, tid);
    }
    cp_commit();

    int buf = 0;
    for (int tt = t0; tt < ntiles; tt += gridDim.x) {
        cp_wait1();                 // tile tt staged (own copies done)
        __syncthreads();            // visible to all warps
        const Tile* tp = &tiles[buf];
        const int base = tt * T;
        const int le0 = warp * 32;  // this warp's 32 edges within the tile
        const int nv = E - base - le0;   // #valid edges for this warp (may be <=0)

        // --- depth-2 x-gather pipeline over the warp's 32 edges ---
        int   rA = tp->row[le0],     cA = tp->col[le0];     float wA = tp->ew[le0];
        int   rB = tp->row[le0 + 1], cB = tp->col[le0 + 1]; float wB = tp->ew[le0 + 1];
        float4 xA = __ldg((const float4*)x + rA * 32 + lane);
        float  ivA = __ldg(g_inv_row + rA) * __ldg(g_inv_col + cA);
        float4 xB = __ldg((const float4*)x + rB * 32 + lane);
        float  ivB = __ldg(g_inv_row + rB) * __ldg(g_inv_col + cB);

        #pragma unroll 4
        for (int i = 0; i < 32; ++i) {
            // prefetch edge i+2
            int rC = 0, cC = 0; float wC = 0.f; float ivC = 0.f;
            float4 xC = make_float4(0.f, 0.f, 0.f, 0.f);
            if (i + 2 < 32) {
                rC = tp->row[le0 + i + 2];
                cC = tp->col[le0 + i + 2];
                wC = tp->ew [le0 + i + 2];
                xC  = __ldg((const float4*)x + rC * 32 + lane);
                ivC = __ldg(g_inv_row + rC) * __ldg(g_inv_col + cC);
            }

            if (i < nv) {
                // attr: broadcast LDS.128 -> FFMA2 operand pairs directly
                const ulonglong2* ap = (const ulonglong2*)(tp->attr + (le0 + i) * BF);
                const ulonglong2 q0 = ap[0], q1 = ap[1], q2 = ap[2], q3 = ap[3];
                const unsigned long long P[8] =
                    {q0.x, q0.y, q1.x, q1.y, q2.x, q2.y, q3.x, q3.y};

                unsigned long long acc0 = B0, acc1 = B1, acc2 = B2, acc3 = B3;
                #pragma unroll
                for (int kp = 0; kp < 8; ++kp) {
                    asm("fma.rn.f32x2 %0, %1, %2, %0;" : "+l"(acc0) : "l"(P[kp]), "l"(W2[kp][0]));
                    asm("fma.rn.f32x2 %0, %1, %2, %0;" : "+l"(acc1) : "l"(P[kp]), "l"(W2[kp][1]));
                    asm("fma.rn.f32x2 %0, %1, %2, %0;" : "+l"(acc2) : "l"(P[kp]), "l"(W2[kp][2]));
                    asm("fma.rn.f32x2 %0, %1, %2, %0;" : "+l"(acc3) : "l"(P[kp]), "l"(W2[kp][3]));
                }
                float lo0, hi0, lo1, hi1, lo2, hi2, lo3, hi3;
                asm("mov.b64 {%0,%1}, %2;" : "=f"(lo0), "=f"(hi0) : "l"(acc0));
                asm("mov.b64 {%0,%1}, %2;" : "=f"(lo1), "=f"(hi1) : "l"(acc1));
                asm("mov.b64 {%0,%1}, %2;" : "=f"(lo2), "=f"(hi2) : "l"(acc2));
                asm("mov.b64 {%0,%1}, %2;" : "=f"(lo3), "=f"(hi3) : "l"(acc3));

                const float v0 = xA.x + (lo0 + hi0);
                const float v1 = xA.y + (lo1 + hi1);
                const float v2 = xA.z + (lo2 + hi2);
                const float v3 = xA.w + (lo3 + hi3);

                const float h = 0.5f * ivA * wA;
                const float tt0 = erff(v0 * 0.70710678118654752440f);
                const float tt1 = erff(v1 * 0.70710678118654752440f);
                const float tt2 = erff(v2 * 0.70710678118654752440f);
                const float tt3 = erff(v3 * 0.70710678118654752440f);
                const float vh0 = v0 * h, vh1 = v1 * h, vh2 = v2 * h, vh3 = v3 * h;
                const float m0 = fmaf(vh0, tt0, vh0);
                const float m1 = fmaf(vh1, tt1, vh1);
                const float m2 = fmaf(vh2, tt2, vh2);
                const float m3 = fmaf(vh3, tt3, vh3);

                float* dst = &g_accum[(size_t)cA * C + lane * 4];
                asm volatile("red.global.add.v4.f32 [%0], {%1, %2, %3, %4};"
                             :: "l"(dst), "f"(m0), "f"(m1), "f"(m2), "f"(m3) : "memory");
            }

            // rotate (renamed away under unroll)
            rA = rB; cA = cB; wA = wB; xA = xB; ivA = ivB;
            rB = rC; cB = cC; wB = wC; xB = xC; ivB = ivC;
        }

        __syncthreads();            // all warps done reading tiles[buf]
        const int tn = tt + 2 * gridDim.x;
        if (tn < ntiles) stage_tile(&tiles[buf], tn * T, E, edge_attr, ei, ew, tid);
        cp_commit();                // exactly one group per iteration
        buf ^= 1;
    }
}

// ---------------------------------------------------------------------------
// Kernel 5: out = (g_accum + selfloop_msg) @ W_lin + b_lin.
// Self-loop message folded here: gelu(x[n]) * inv_r[n] * inv_c[n] (ew = 1).
// ---------------------------------------------------------------------------
__global__ __launch_bounds__(128) void k_out(
    const float* __restrict__ Wl,
    const float* __restrict__ bl,
    const float* __restrict__ x,
    float* __restrict__ out,
    int N)
{
    __shared__ float sx[8][C];
    const int n0 = blockIdx.x * 8;
    const int j  = threadIdx.x;

    #pragma unroll
    for (int r = 0; r < 8; ++r) {
        int n = n0 + r;
        if (n < N) {
            const float v = x[(size_t)n * C + j];
            const float g = 0.5f * v * (1.0f + erff(v * 0.70710678118654752440f));
            const float iv = g_inv_row[n] * g_inv_col[n];
            sx[r][j] = g_accum[(size_t)n * C + j] + g * iv;
        } else {
            sx[r][j] = 0.0f;
        }
    }
    __syncthreads();

    float a0 = 0.f, a1 = 0.f, a2 = 0.f, a3 = 0.f;
    float a4 = 0.f, a5 = 0.f, a6 = 0.f, a7 = 0.f;
    #pragma unroll 4
    for (int c = 0; c < C; ++c) {
        const float wv = Wl[c * C + j];
        a0 += sx[0][c] * wv;  a1 += sx[1][c] * wv;
        a2 += sx[2][c] * wv;  a3 += sx[3][c] * wv;
        a4 += sx[4][c] * wv;  a5 += sx[5][c] * wv;
        a6 += sx[6][c] * wv;  a7 += sx[7][c] * wv;
    }
    const float b = bl[j];
    float acc[8] = {a0, a1, a2, a3, a4, a5, a6, a7};
    #pragma unroll
    for (int r = 0; r < 8; ++r) {
        int n = n0 + r;
        if (n < N) out[(size_t)n * C + j] = acc[r] + b;
    }
}

// ---------------------------------------------------------------------------
// Launch: linear chain of 5 kernels on the capture stream.
// ---------------------------------------------------------------------------
extern "C" void kernel_launch(void* const* d_in, const int* in_sizes, int n_in,
                              void* d_out, int out_size)
{
    const float* x         = (const float*)d_in[0];   // [N, 128]
    const float* edge_attr = (const float*)d_in[1];   // [E, 16]
    const float* ew        = (const float*)d_in[2];   // [E, 1]
    const float* Wb        = (const float*)d_in[3];   // [16, 128]
    const float* bb        = (const float*)d_in[4];   // [128]
    const float* Wl        = (const float*)d_in[5];   // [128, 128]
    const float* bl        = (const float*)d_in[6];   // [128]
    const int*   ei        = (const int*)d_in[7];     // [2, E]
    float*       out       = (float*)d_out;           // [N, 128]

    const int E = in_sizes[2];          // edge_weight element count
    const int N = in_sizes[0] / C;      // x rows

    {   // init accumulator (float4) + degree seeds
        int threads = 256;
        int blocks = (N * (C / 4) + threads - 1) / threads;
        k_init<<<blocks, threads>>>(N);
    }
    {
        int threads = 256;
        int work = (E + 3) / 4;
        int blocks = (work + threads - 1) / threads;
        k_deg<<<blocks, threads>>>(ei, E);
    }
    {
        int threads = 256;
        int blocks = (N + threads - 1) / threads;
        k_inv<<<blocks, threads>>>(N);
    }
    {
        int ntiles = (E + T - 1) / T;
        int blocks = (ntiles < NBLK) ? ntiles : NBLK;
        k_msg<<<blocks, 128>>>(x, edge_attr, ew, Wb, bb, ei, E);
    }
    {
        int blocks = (N + 7) / 8;
        k_out<<<blocks, 128>>>(Wl, bl, x, out, N);
    }
}